// round 1
// baseline (speedup 1.0000x reference)
#include <cuda_runtime.h>
#include <math.h>

#define KDT   0.1f
#define KG    9.81f
#define KRHO  1028.0f

// Constant block layout (floats):
// [0:36)    Minv
// [36:72)   mTot
// [72:108)  linDamp
// [108:144) linDampFow
// [144:180) quadDamp
// [180:183) cog
// [183:186) cob
// [186]     mass
// [187]     volume
__device__ float g_consts[188];

__global__ void prep_kernel(const float* mass, const float* volume,
                            const float* cog, const float* cob,
                            const float* mTot, const float* linDamp,
                            const float* linDampFow, const float* quadDamp) {
    if (threadIdx.x != 0 || blockIdx.x != 0) return;
    for (int i = 0; i < 36; i++) {
        g_consts[36 + i]  = mTot[i];
        g_consts[72 + i]  = linDamp[i];
        g_consts[108 + i] = linDampFow[i];
        g_consts[144 + i] = quadDamp[i];
    }
    for (int i = 0; i < 3; i++) { g_consts[180 + i] = cog[i]; g_consts[183 + i] = cob[i]; }
    g_consts[186] = mass[0];
    g_consts[187] = volume[0];

    // Gauss-Jordan 6x6 inverse with partial pivoting
    float A[6][6], B[6][6];
    for (int i = 0; i < 6; i++)
        for (int j = 0; j < 6; j++) {
            A[i][j] = mTot[i * 6 + j];
            B[i][j] = (i == j) ? 1.0f : 0.0f;
        }
    for (int c = 0; c < 6; c++) {
        int piv = c; float best = fabsf(A[c][c]);
        for (int r = c + 1; r < 6; r++) {
            float a = fabsf(A[r][c]);
            if (a > best) { best = a; piv = r; }
        }
        if (piv != c) {
            for (int j = 0; j < 6; j++) {
                float t = A[c][j]; A[c][j] = A[piv][j]; A[piv][j] = t;
                t = B[c][j]; B[c][j] = B[piv][j]; B[piv][j] = t;
            }
        }
        float inv = 1.0f / A[c][c];
        for (int j = 0; j < 6; j++) { A[c][j] *= inv; B[c][j] *= inv; }
        for (int r = 0; r < 6; r++) {
            if (r == c) continue;
            float f = A[r][c];
            for (int j = 0; j < 6; j++) { A[r][j] -= f * A[c][j]; B[r][j] -= f * B[c][j]; }
        }
    }
    for (int i = 0; i < 6; i++)
        for (int j = 0; j < 6; j++)
            g_consts[i * 6 + j] = B[i][j];
}

// Computes xdot for one state (q, v) with control uu.
// pd[7]: pDot (3 lin + 4 quat), vd[6]: vDot.
__device__ __forceinline__ void fossen_dot(const float* __restrict__ sc,
                                           const float q[4], const float v[6],
                                           const float uu[6],
                                           float pd[7], float vd[6]) {
    const float qx = q[0], qy = q[1], qz = q[2], qw = q[3];

    // Rotation matrix (body->inertial) from (possibly unnormalized) quaternion,
    // exactly as the reference builds it.
    const float r00 = 1.0f - 2.0f * (qy * qy + qz * qz);
    const float r01 = 2.0f * (qx * qy - qz * qw);
    const float r02 = 2.0f * (qx * qz + qy * qw);
    const float r10 = 2.0f * (qx * qy + qz * qw);
    const float r11 = 1.0f - 2.0f * (qx * qx + qz * qz);
    const float r12 = 2.0f * (qy * qz - qx * qw);
    const float r20 = 2.0f * (qx * qz - qy * qw);
    const float r21 = 2.0f * (qy * qz + qx * qw);
    const float r22 = 1.0f - 2.0f * (qx * qx + qy * qy);

    const float v0 = v[0], v1 = v[1], v2 = v[2];
    const float w0 = v[3], w1 = v[4], w2 = v[5];

    // pDot_lin = rot @ v_lin
    pd[0] = r00 * v0 + r01 * v1 + r02 * v2;
    pd[1] = r10 * v0 + r11 * v1 + r12 * v2;
    pd[2] = r20 * v0 + r21 * v1 + r22 * v2;
    // pDot_ang = T(q) @ w  (quaternion kinematics)
    pd[3] = 0.5f * (-qx * w0 - qy * w1 - qz * w2);
    pd[4] = 0.5f * ( qw * w0 - qz * w1 + qy * w2);
    pd[5] = 0.5f * ( qz * w0 + qw * w1 - qx * w2);
    pd[6] = 0.5f * (-qy * w0 + qx * w1 + qw * w2);

    // Dv: D[i][j] = -linDamp[i][j] - v_i*linDampFow[i][j] - quadDamp[i][i]*|v_i|*delta_ij
    float Dv[6];
#pragma unroll
    for (int i = 0; i < 6; i++) {
        const float vi = v[i];
        float acc = 0.0f;
#pragma unroll
        for (int j = 0; j < 6; j++) {
            const float d = -sc[72 + i * 6 + j] - vi * sc[108 + i * 6 + j];
            acc += d * v[j];
        }
        acc -= sc[144 + i * 6 + i] * fabsf(vi) * vi;
        Dv[i] = acc;
    }

    // Coriolis: mvt = M[0:3,:] v, mvb = M[3:6,:] v
    float mvt[3], mvb[3];
#pragma unroll
    for (int i = 0; i < 3; i++) {
        float a = 0.0f, b = 0.0f;
#pragma unroll
        for (int j = 0; j < 6; j++) {
            a += sc[36 + i * 6 + j] * v[j];
            b += sc[36 + (i + 3) * 6 + j] * v[j];
        }
        mvt[i] = a; mvb[i] = b;
    }
    // Cv_top = -(mvt x w); Cv_bot = -(mvt x v_lin) - (mvb x w)
    float Cv[6];
    Cv[0] = -(mvt[1] * w2 - mvt[2] * w1);
    Cv[1] = -(mvt[2] * w0 - mvt[0] * w2);
    Cv[2] = -(mvt[0] * w1 - mvt[1] * w0);
    Cv[3] = -(mvt[1] * v2 - mvt[2] * v1) - (mvb[1] * w2 - mvb[2] * w1);
    Cv[4] = -(mvt[2] * v0 - mvt[0] * v2) - (mvb[2] * w0 - mvb[0] * w2);
    Cv[5] = -(mvt[0] * v1 - mvt[1] * v0) - (mvb[0] * w1 - mvb[1] * w0);

    // Restoring: fbg = rot^T * (0,0,-m g); fbb = rot^T * (0,0,V rho g)
    const float fgz = -sc[186] * KG;
    const float fbz = sc[187] * KRHO * KG;
    const float fbg0 = r20 * fgz, fbg1 = r21 * fgz, fbg2 = r22 * fgz;
    const float fbb0 = r20 * fbz, fbb1 = r21 * fbz, fbb2 = r22 * fbz;
    const float cg0 = sc[180], cg1 = sc[181], cg2 = sc[182];
    const float cb0 = sc[183], cb1 = sc[184], cb2 = sc[185];
    // mbg = cog x fbg; mbb = cob x fbb
    const float mbg0 = cg1 * fbg2 - cg2 * fbg1;
    const float mbg1 = cg2 * fbg0 - cg0 * fbg2;
    const float mbg2 = cg0 * fbg1 - cg1 * fbg0;
    const float mbb0 = cb1 * fbb2 - cb2 * fbb1;
    const float mbb1 = cb2 * fbb0 - cb0 * fbb2;
    const float mbb2 = cb0 * fbb1 - cb1 * fbb0;
    // g = -[fbg+fbb ; mbg+mbb]
    float gres[6];
    gres[0] = -(fbg0 + fbb0);
    gres[1] = -(fbg1 + fbb1);
    gres[2] = -(fbg2 + fbb2);
    gres[3] = -(mbg0 + mbb0);
    gres[4] = -(mbg1 + mbb1);
    gres[5] = -(mbg2 + mbb2);

    // rhs = u - Cv - Dv - g;  vDot = Minv @ rhs
    float rhs[6];
#pragma unroll
    for (int i = 0; i < 6; i++) rhs[i] = uu[i] - Cv[i] - Dv[i] - gres[i];
#pragma unroll
    for (int i = 0; i < 6; i++) {
        float acc = 0.0f;
#pragma unroll
        for (int j = 0; j < 6; j++) acc += sc[i * 6 + j] * rhs[j];
        vd[i] = acc;
    }
}

__global__ __launch_bounds__(256) void auv_kernel(const float* __restrict__ x,
                                                  const float* __restrict__ u,
                                                  float* __restrict__ out, int K) {
    __shared__ float sx[256 * 13];
    __shared__ float su[256 * 6];
    __shared__ float sc[188];

    const int tid = threadIdx.x;
    const int rbase = blockIdx.x * 256;
    const int total_x = K * 13;
    const int total_u = K * 6;

    if (tid < 188) sc[tid] = g_consts[tid];

    // Coalesced staged loads
#pragma unroll
    for (int i = tid; i < 256 * 13; i += 256) {
        int g = rbase * 13 + i;
        sx[i] = (g < total_x) ? x[g] : 0.0f;
    }
#pragma unroll
    for (int i = tid; i < 256 * 6; i += 256) {
        int g = rbase * 6 + i;
        su[i] = (g < total_u) ? u[g] : 0.0f;
    }
    __syncthreads();

    const int row = rbase + tid;
    const bool active = (row < K);

    float pos[3], q[4], v[6], uu[6];
    const float* mx = &sx[tid * 13];
#pragma unroll
    for (int i = 0; i < 3; i++) pos[i] = mx[i];
#pragma unroll
    for (int i = 0; i < 4; i++) q[i] = mx[3 + i];
#pragma unroll
    for (int i = 0; i < 6; i++) v[i] = mx[7 + i];
#pragma unroll
    for (int i = 0; i < 6; i++) uu[i] = su[tid * 6 + i];

    float pd1[7], vd1[6], pd2[7], vd2[6];
    fossen_dot(sc, q, v, uu, pd1, vd1);

    float q2[4], v2[6];
#pragma unroll
    for (int i = 0; i < 4; i++) q2[i] = q[i] + KDT * pd1[3 + i];
#pragma unroll
    for (int i = 0; i < 6; i++) v2[i] = v[i] + KDT * vd1[i];

    fossen_dot(sc, q2, v2, uu, pd2, vd2);

    const float hdt = 0.5f * KDT;
    float res[13];
#pragma unroll
    for (int i = 0; i < 3; i++) res[i] = pos[i] + hdt * (pd1[i] + pd2[i]);
    float qo[4];
#pragma unroll
    for (int i = 0; i < 4; i++) qo[i] = q[i] + hdt * (pd1[3 + i] + pd2[3 + i]);
    const float qn = rsqrtf(qo[0] * qo[0] + qo[1] * qo[1] + qo[2] * qo[2] + qo[3] * qo[3]);
#pragma unroll
    for (int i = 0; i < 4; i++) res[3 + i] = qo[i] * qn;
#pragma unroll
    for (int i = 0; i < 6; i++) res[7 + i] = v[i] + hdt * (vd1[i] + vd2[i]);

    // Stage results back into sx (each thread owns its own 13-slot slice)
    float* ox = &sx[tid * 13];
    if (active) {
#pragma unroll
        for (int i = 0; i < 13; i++) ox[i] = res[i];
    }
    __syncthreads();

    // Coalesced staged stores
#pragma unroll
    for (int i = tid; i < 256 * 13; i += 256) {
        int g = rbase * 13 + i;
        if (g < total_x) out[g] = sx[i];
    }
}

extern "C" void kernel_launch(void* const* d_in, const int* in_sizes, int n_in,
                              void* d_out, int out_size) {
    const float* x          = (const float*)d_in[0];
    const float* u          = (const float*)d_in[1];
    const float* mass       = (const float*)d_in[2];
    const float* volume     = (const float*)d_in[3];
    const float* cog        = (const float*)d_in[4];
    const float* cob        = (const float*)d_in[5];
    const float* mTot       = (const float*)d_in[6];
    const float* linDamp    = (const float*)d_in[7];
    const float* linDampFow = (const float*)d_in[8];
    const float* quadDamp   = (const float*)d_in[9];

    const int K = in_sizes[0] / 13;

    prep_kernel<<<1, 1>>>(mass, volume, cog, cob, mTot, linDamp, linDampFow, quadDamp);

    const int blocks = (K + 255) / 256;
    auv_kernel<<<blocks, 256>>>(x, u, (float*)d_out, K);
}